// round 7
// baseline (speedup 1.0000x reference)
#include <cuda_runtime.h>
#include <cuda_bf16.h>
#include <cstdint>

// Problem dims (fixed by dataset)
#define M_DIM 8192
#define N_DIM 8192
#define D_DIM 512
#define BM 128
#define BN 128
#define BK 64                 // int8 elems per K-chunk = 64 B rows
#define NCHUNK (D_DIM / BK)   // 8
#define NBN (N_DIM / BN)      // 64
#define STAGES 3
#define ROW_PITCH 80          // 64B data + 16B pad: conflict-free ldmatrix, 16B-aligned
#define STG_TILE 10240        // 128 rows * 80 B
#define STG_BYTES 20480       // A + B per stage

#define QSCALE 16.0f          // quantization scale: x*16 -> s8
#define INV_QQ (1.0f / 256.0f)

// SMEM offsets (dynamic)
#define OFF_Q   (STAGES * STG_BYTES)          // 61440: 128 floats (gamma*yy)
#define OFF_W   (OFF_Q + 512)                 // 61952: 128 floats (weight)
#define OFF_RED (OFF_W + 512)                 // 62464: 2 x 128 floats
#define SMEM_BYTES (OFF_RED + 1024)           // 63488

// ---------------- device scratch (no cudaMalloc allowed) ----------------
__device__ int8_t g_Xq[(size_t)M_DIM * D_DIM];   // 4 MB
__device__ int8_t g_Yq[(size_t)N_DIM * D_DIM];   // 4 MB
__device__ float g_xx[M_DIM];
__device__ float g_yy[N_DIM];
__device__ float g_partial[(size_t)NBN * M_DIM]; // 2 MB

__device__ __forceinline__ uint32_t smem_u32(const void* p) {
    uint32_t a;
    asm("{ .reg .u64 t; cvta.to.shared.u64 t, %1; cvt.u32.u64 %0, t; }" : "=r"(a) : "l"(p));
    return a;
}
__device__ __forceinline__ void cp_async16(uint32_t saddr, const void* gaddr) {
    asm volatile("cp.async.cg.shared.global [%0], [%1], 16;" :: "r"(saddr), "l"(gaddr));
}
#define CP_COMMIT() asm volatile("cp.async.commit_group;" ::: "memory")
__device__ __forceinline__ void ldmatrix_x4(uint32_t& r0, uint32_t& r1, uint32_t& r2,
                                            uint32_t& r3, uint32_t addr) {
    asm volatile("ldmatrix.sync.aligned.m8n8.x4.shared.b16 {%0,%1,%2,%3}, [%4];"
                 : "=r"(r0), "=r"(r1), "=r"(r2), "=r"(r3) : "r"(addr));
}
// s8 IMMA, k32, s32 accum. Same fragment bytes as the fp8 k32 form.
__device__ __forceinline__ void mma_s8(int* c, uint32_t a0, uint32_t a1, uint32_t a2,
                                       uint32_t a3, uint32_t b0, uint32_t b1) {
    asm volatile("mma.sync.aligned.m16n8k32.row.col.s32.s8.s8.s32 "
                 "{%0,%1,%2,%3}, {%4,%5,%6,%7}, {%8,%9}, {%0,%1,%2,%3};"
                 : "+r"(c[0]), "+r"(c[1]), "+r"(c[2]), "+r"(c[3])
                 : "r"(a0), "r"(a1), "r"(a2), "r"(a3), "r"(b0), "r"(b1));
}
__device__ __forceinline__ uint32_t q8(float v) {
    int q = __float2int_rn(v * QSCALE);
    q = max(-127, min(127, q));
    return (uint32_t)q & 0xffu;
}

// ---------------------------------------------------------------------------
// Prologue: fp32 -> s8 quantization (scale 16) fused with fp32 row norms.
// ---------------------------------------------------------------------------
__global__ void prep_kernel(const float* __restrict__ X, const float* __restrict__ Y) {
    const int row = blockIdx.x;
    const bool isY = (blockIdx.y != 0);
    const float* src = isY ? Y : X;
    int8_t* dst = isY ? g_Yq : g_Xq;

    const float4 v = *(const float4*)(src + (size_t)row * D_DIM + threadIdx.x * 4);
    float s = v.x * v.x + v.y * v.y + v.z * v.z + v.w * v.w;

    const uint32_t packed = q8(v.x) | (q8(v.y) << 8) | (q8(v.z) << 16) | (q8(v.w) << 24);
    *reinterpret_cast<uint32_t*>(dst + (size_t)row * D_DIM + threadIdx.x * 4) = packed;

    #pragma unroll
    for (int off = 16; off > 0; off >>= 1) s += __shfl_down_sync(0xffffffffu, s, off);
    __shared__ float ws[4];
    const int lane = threadIdx.x & 31, w = threadIdx.x >> 5;
    if (lane == 0) ws[w] = s;
    __syncthreads();
    if (threadIdx.x == 0) {
        const float t = ws[0] + ws[1] + ws[2] + ws[3];
        if (isY) g_yy[row] = t; else g_xx[row] = t;
    }
}

// ---------------------------------------------------------------------------
// Main kernel: s8 IMMA GEMM (128x128 tile, K=512) + fused RBF epilogue.
// 8 warps in 4(M) x 2(N); warp tile 32x64. 3-stage cp.async pipeline.
// ---------------------------------------------------------------------------
__device__ __forceinline__ void load_stage(uint32_t sb, int s, int c,
                                           int rowBase, int colBase, int tid) {
    const int k0 = c * BK;   // byte offset within a row (1 B per elem)
    #pragma unroll
    for (int i = 0; i < 2; i++) {
        const int idx = tid + i * 256;
        const int r = idx >> 2, c16 = idx & 3;
        const uint32_t so = (uint32_t)(s * STG_BYTES + r * ROW_PITCH + c16 * 16);
        cp_async16(sb + so, g_Xq + (size_t)(rowBase + r) * D_DIM + k0 + c16 * 16);
        cp_async16(sb + so + STG_TILE, g_Yq + (size_t)(colBase + r) * D_DIM + k0 + c16 * 16);
    }
}

__global__ __launch_bounds__(256, 2)
void rbf_mma_kernel(const float* __restrict__ gamma_p, const float* __restrict__ W) {
    extern __shared__ char smem[];
    const uint32_t sb = smem_u32(smem);
    const int tid = threadIdx.x;
    const int w = tid >> 5, l = tid & 31;
    const int wm = w & 3, wn = w >> 2;         // 4 x 2 warp grid
    const int m0w = wm * 32, n0w = wn * 64;
    const int bn = blockIdx.x, bm = blockIdx.y;
    const int rowBase = bm * BM, colBase = bn * BN;

    const float g = gamma_p[0];
    if (tid < 128) {
        ((float*)(smem + OFF_Q))[tid] = g * g_yy[colBase + tid];
        ((float*)(smem + OFF_W))[tid] = W[colBase + tid];
    }

    int acc[2][8][4];
    #pragma unroll
    for (int mt = 0; mt < 2; mt++)
        #pragma unroll
        for (int nt = 0; nt < 8; nt++)
            #pragma unroll
            for (int i = 0; i < 4; i++) acc[mt][nt][i] = 0;

    load_stage(sb, 0, 0, rowBase, colBase, tid); CP_COMMIT();
    load_stage(sb, 1, 1, rowBase, colBase, tid); CP_COMMIT();

    const uint32_t a_lane = (uint32_t)((m0w + (l & 15)) * ROW_PITCH + ((l >> 4) * 16));
    const uint32_t b_lane = (uint32_t)(STG_TILE + (n0w + (l & 15)) * ROW_PITCH + ((l >> 4) * 16));

    #pragma unroll 1
    for (int c = 0; c < NCHUNK; c++) {
        if (c == NCHUNK - 1) asm volatile("cp.async.wait_group 0;" ::: "memory");
        else                 asm volatile("cp.async.wait_group 1;" ::: "memory");
        __syncthreads();
        if (c + 2 < NCHUNK) {
            load_stage(sb, (c + 2) % STAGES, c + 2, rowBase, colBase, tid);
            CP_COMMIT();
        }
        const uint32_t stg = sb + (uint32_t)((c % STAGES) * STG_BYTES);
        #pragma unroll
        for (int kk = 0; kk < 2; kk++) {                 // two k32 steps per BK=64
            const uint32_t ko = (uint32_t)(kk * 32);     // 32 s8 = 32 B
            uint32_t a[2][4], b[4][4];
            #pragma unroll
            for (int mt = 0; mt < 2; mt++)
                ldmatrix_x4(a[mt][0], a[mt][1], a[mt][2], a[mt][3],
                            stg + a_lane + mt * (16 * ROW_PITCH) + ko);
            #pragma unroll
            for (int nt2 = 0; nt2 < 4; nt2++)
                ldmatrix_x4(b[nt2][0], b[nt2][1], b[nt2][2], b[nt2][3],
                            stg + b_lane + nt2 * (16 * ROW_PITCH) + ko);
            #pragma unroll
            for (int mt = 0; mt < 2; mt++)
                #pragma unroll
                for (int nt = 0; nt < 8; nt++) {
                    const int h = nt >> 1, o = nt & 1;
                    mma_s8(acc[mt][nt], a[mt][0], a[mt][1], a[mt][2], a[mt][3],
                           b[h][o], b[h][o + 2]);
                }
        }
    }
    __syncthreads();

    // ---- fused epilogue straight from register fragments ----
    // xy_true ~= acc * (1/256); fold into m2g.
    const float* qsh = (const float*)(smem + OFF_Q);
    const float* wsh = (const float*)(smem + OFF_W);
    const float m2g = -2.0f * g * INV_QQ;
    float rs[2][2] = {{0.0f, 0.0f}, {0.0f, 0.0f}};   // [mt][lo/hi]
    float gxx[2][2];
    #pragma unroll
    for (int mt = 0; mt < 2; mt++)
        #pragma unroll
        for (int h = 0; h < 2; h++)
            gxx[mt][h] = g * g_xx[rowBase + m0w + mt * 16 + (l >> 2) + 8 * h];

    #pragma unroll
    for (int mt = 0; mt < 2; mt++)
        #pragma unroll
        for (int nt = 0; nt < 8; nt++) {
            const int n = n0w + nt * 8 + (l & 3) * 2;
            const float q0 = qsh[n], q1 = qsh[n + 1];
            const float w0 = wsh[n], w1 = wsh[n + 1];
            const int* cc = acc[mt][nt];
            // exp underflows to exactly 0 in fp32 for arg > ~104: gate MUFU
            float t;
            t = fmaf(m2g, (float)cc[0], gxx[mt][0] + q0);
            if (t < 110.0f) rs[mt][0] = fmaf(__expf(-fmaxf(t, 0.0f)), w0, rs[mt][0]);
            t = fmaf(m2g, (float)cc[1], gxx[mt][0] + q1);
            if (t < 110.0f) rs[mt][0] = fmaf(__expf(-fmaxf(t, 0.0f)), w1, rs[mt][0]);
            t = fmaf(m2g, (float)cc[2], gxx[mt][1] + q0);
            if (t < 110.0f) rs[mt][1] = fmaf(__expf(-fmaxf(t, 0.0f)), w0, rs[mt][1]);
            t = fmaf(m2g, (float)cc[3], gxx[mt][1] + q1);
            if (t < 110.0f) rs[mt][1] = fmaf(__expf(-fmaxf(t, 0.0f)), w1, rs[mt][1]);
        }

    float* red = (float*)(smem + OFF_RED);   // [2][128]
    #pragma unroll
    for (int mt = 0; mt < 2; mt++)
        #pragma unroll
        for (int h = 0; h < 2; h++) {
            float v = rs[mt][h];
            v += __shfl_xor_sync(0xffffffffu, v, 1);
            v += __shfl_xor_sync(0xffffffffu, v, 2);
            if ((l & 3) == 0)
                red[wn * 128 + m0w + mt * 16 + (l >> 2) + 8 * h] = v;
        }
    __syncthreads();
    if (tid < 128)
        g_partial[(size_t)bn * M_DIM + rowBase + tid] = red[tid] + red[128 + tid];
}

// ---------------------------------------------------------------------------
// Final deterministic reduction over 64 column blocks + bias.
// ---------------------------------------------------------------------------
__global__ void reduce_kernel(float* __restrict__ out, const float* __restrict__ bias) {
    const int m = blockIdx.x * blockDim.x + threadIdx.x;
    float s = bias[0];
    #pragma unroll
    for (int b = 0; b < NBN; b++) s += g_partial[(size_t)b * M_DIM + m];
    out[m] = s;
}

// ---------------------------------------------------------------------------
extern "C" void kernel_launch(void* const* d_in, const int* in_sizes, int n_in,
                              void* d_out, int out_size) {
    const float* x       = (const float*)d_in[0];
    const float* x_train = (const float*)d_in[1];
    const float* gamma   = (const float*)d_in[2];
    const float* weight  = (const float*)d_in[3];
    const float* bias    = (const float*)d_in[4];
    float* out = (float*)d_out;

    cudaFuncSetAttribute(rbf_mma_kernel, cudaFuncAttributeMaxDynamicSharedMemorySize, SMEM_BYTES);

    prep_kernel<<<dim3(M_DIM, 2), 128>>>(x, x_train);
    rbf_mma_kernel<<<dim3(NBN, M_DIM / BM), 256, SMEM_BYTES>>>(gamma, weight);
    reduce_kernel<<<M_DIM / 256, 256>>>(out, bias);
}

// round 14
// speedup vs baseline: 3.2926x; 3.2926x over previous
#include <cuda_runtime.h>
#include <cuda_fp16.h>
#include <cstdint>

// Problem dims (fixed by dataset)
#define M_DIM 8192
#define N_DIM 8192
#define D_DIM 512
#define DP    192             // projected dims for the certificate GEMM (3 chunks)
#define BM 128
#define BN 128
#define BK 64                 // fp8 elems per K-chunk = 64 B rows
#define NCHUNK (DP / BK)      // 3
#define NBN (N_DIM / BN)      // 64
#define STAGES 3
#define ROW_PITCH 80          // 64B data + 16B pad: conflict-free ldmatrix, 16B-aligned
#define STG_TILE 10240        // 128 rows * 80 B
#define STG_BYTES 20480       // A + B per stage
#define FCAP 1024             // per-CTA smem flag capacity

// SMEM offsets (dynamic)
#define OFF_Q     (STAGES * STG_BYTES)        // 61440: 128 floats (yyp)
#define OFF_FLAGS (OFF_Q + 512)               // 61952: FCAP u32
#define OFF_NF    (OFF_FLAGS + FCAP * 4)      // 66048: counter
#define SMEM_BYTES (OFF_NF + 16)              // 66064

// ---------------- device scratch (no cudaMalloc allowed) ----------------
__device__ uint8_t g_Xq[(size_t)M_DIM * D_DIM];   // 4 MB, e4m3
__device__ uint8_t g_Yq[(size_t)N_DIM * D_DIM];   // 4 MB, e4m3
__device__ float g_xx[M_DIM];     // exact fp32 norms, all 512 dims (fallback)
__device__ float g_yy[N_DIM];
__device__ float g_xxp[M_DIM];    // ||dequant(x)||^2 over first DP dims
__device__ float g_yyp[N_DIM];
__device__ unsigned g_Emax_bits;  // max_m ||x_P - dequant(x)_P|| (float bits, >=0)
__device__ unsigned g_Fmax_bits;  // idem for Y; monotone across replays (deterministic)

__device__ __forceinline__ uint32_t smem_u32(const void* p) {
    uint32_t a;
    asm("{ .reg .u64 t; cvta.to.shared.u64 t, %1; cvt.u32.u64 %0, t; }" : "=r"(a) : "l"(p));
    return a;
}
__device__ __forceinline__ void cp_async16(uint32_t saddr, const void* gaddr) {
    asm volatile("cp.async.cg.shared.global [%0], [%1], 16;" :: "r"(saddr), "l"(gaddr));
}
#define CP_COMMIT() asm volatile("cp.async.commit_group;" ::: "memory")
__device__ __forceinline__ void ldmatrix_x4(uint32_t& r0, uint32_t& r1, uint32_t& r2,
                                            uint32_t& r3, uint32_t addr) {
    asm volatile("ldmatrix.sync.aligned.m8n8.x4.shared.b16 {%0,%1,%2,%3}, [%4];"
                 : "=r"(r0), "=r"(r1), "=r"(r2), "=r"(r3) : "r"(addr));
}
__device__ __forceinline__ void mma_fp8(float* c, uint32_t a0, uint32_t a1, uint32_t a2,
                                        uint32_t a3, uint32_t b0, uint32_t b1) {
    asm volatile("mma.sync.aligned.m16n8k32.row.col.f32.e4m3.e4m3.f32 "
                 "{%0,%1,%2,%3}, {%4,%5,%6,%7}, {%8,%9}, {%0,%1,%2,%3};"
                 : "+f"(c[0]), "+f"(c[1]), "+f"(c[2]), "+f"(c[3])
                 : "r"(a0), "r"(a1), "r"(a2), "r"(a3), "r"(b0), "r"(b1));
}
__device__ __forceinline__ uint16_t pack_e4m3x2(float lo, float hi) {
    uint16_t d;
    asm("cvt.rn.satfinite.e4m3x2.f32 %0, %1, %2;" : "=h"(d) : "f"(hi), "f"(lo));
    return d;
}
__device__ __forceinline__ float2 dequant_e4m3x2(uint16_t h) {
    uint32_t f16x2;
    asm("cvt.rn.f16x2.e4m3x2 %0, %1;" : "=r"(f16x2) : "h"(h));
    __half2 hh = *reinterpret_cast<__half2*>(&f16x2);
    return __half22float2(hh);
}

// Exact fp32 RBF term for pair (m,n), added to out[m]. Used only for the
// handful of pairs the certificate cannot prove to underflow.
__device__ __forceinline__ void exact_term(const float* __restrict__ X,
                                           const float* __restrict__ Y,
                                           const float* __restrict__ W,
                                           float* __restrict__ out,
                                           float g, int m, int n) {
    const float* xr = X + (size_t)m * D_DIM;
    const float* yr = Y + (size_t)n * D_DIM;
    float dot = 0.0f;
    #pragma unroll 4
    for (int d = 0; d < D_DIM; d += 4) {
        const float4 a = *(const float4*)(xr + d);
        const float4 b = *(const float4*)(yr + d);
        dot += a.x * b.x + a.y * b.y + a.z * b.z + a.w * b.w;
    }
    const float sq = fmaxf(g_xx[m] + g_yy[n] - 2.0f * dot, 0.0f);
    atomicAdd(&out[m], __expf(-g * sq) * W[n]);
}

// ---------------------------------------------------------------------------
// Prologue: fp32 -> e4m3, exact 512-dim norms, projected dequant norms,
// and projected residual norms (self-measuring certificate inputs).
// ---------------------------------------------------------------------------
__global__ void prep_kernel(const float* __restrict__ X, const float* __restrict__ Y) {
    const int row = blockIdx.x;
    const bool isY = (blockIdx.y != 0);
    const float* src = isY ? Y : X;
    uint8_t* dst = isY ? g_Yq : g_Xq;

    const float4 v = *(const float4*)(src + (size_t)row * D_DIM + threadIdx.x * 4);
    float s_full = v.x * v.x + v.y * v.y + v.z * v.z + v.w * v.w;

    const uint16_t p0 = pack_e4m3x2(v.x, v.y);
    const uint16_t p1 = pack_e4m3x2(v.z, v.w);
    *reinterpret_cast<uint32_t*>(dst + (size_t)row * D_DIM + threadIdx.x * 4) =
        (uint32_t)p0 | ((uint32_t)p1 << 16);

    const float2 d0 = dequant_e4m3x2(p0);
    const float2 d1 = dequant_e4m3x2(p1);
    const bool inP = (threadIdx.x < DP / 4);               // first 192 dims
    float xxp = 0.0f, r2 = 0.0f;
    if (inP) {
        xxp = d0.x * d0.x + d0.y * d0.y + d1.x * d1.x + d1.y * d1.y;
        const float e0 = v.x - d0.x, e1 = v.y - d0.y, e2 = v.z - d1.x, e3 = v.w - d1.y;
        r2 = e0 * e0 + e1 * e1 + e2 * e2 + e3 * e3;
    }

    #pragma unroll
    for (int off = 16; off > 0; off >>= 1) {
        s_full += __shfl_down_sync(0xffffffffu, s_full, off);
        xxp    += __shfl_down_sync(0xffffffffu, xxp, off);
        r2     += __shfl_down_sync(0xffffffffu, r2, off);
    }
    __shared__ float ws[3][4];
    const int lane = threadIdx.x & 31, w = threadIdx.x >> 5;
    if (lane == 0) { ws[0][w] = s_full; ws[1][w] = xxp; ws[2][w] = r2; }
    __syncthreads();
    if (threadIdx.x == 0) {
        const float tf = ws[0][0] + ws[0][1] + ws[0][2] + ws[0][3];
        const float tp = ws[1][0] + ws[1][1] + ws[1][2] + ws[1][3];
        const float tr = ws[2][0] + ws[2][1] + ws[2][2] + ws[2][3];
        const unsigned rb = __float_as_uint(sqrtf(tr));
        if (isY) { g_yy[row] = tf; g_yyp[row] = tp; atomicMax(&g_Fmax_bits, rb); }
        else     { g_xx[row] = tf; g_xxp[row] = tp; atomicMax(&g_Emax_bits, rb); }
    }
}

// ---------------------------------------------------------------------------
// out[m] = bias (runs BEFORE the main kernel; certified terms are exactly 0)
// ---------------------------------------------------------------------------
__global__ void bias_kernel(float* __restrict__ out, const float* __restrict__ bias) {
    out[blockIdx.x * blockDim.x + threadIdx.x] = bias[0];
}

// ---------------------------------------------------------------------------
// Main kernel: fp8 GEMM over first 192 dims (certificate). Elements with
// sq~ >= T are PROVEN to underflow exp in fp32 (contribute exactly 0).
// Failures are collected in a per-CTA smem list and recomputed exactly in
// fp32 over all 512 dims by this same CTA (warp-cooperative), added to out.
// ---------------------------------------------------------------------------
__device__ __forceinline__ void load_stage(uint32_t sb, int s, int c,
                                           int rowBase, int colBase, int tid) {
    const int k0 = c * BK;
    #pragma unroll
    for (int i = 0; i < 2; i++) {
        const int idx = tid + i * 256;
        const int r = idx >> 2, c16 = idx & 3;
        const uint32_t so = (uint32_t)(s * STG_BYTES + r * ROW_PITCH + c16 * 16);
        cp_async16(sb + so, g_Xq + (size_t)(rowBase + r) * D_DIM + k0 + c16 * 16);
        cp_async16(sb + so + STG_TILE, g_Yq + (size_t)(colBase + r) * D_DIM + k0 + c16 * 16);
    }
}

__global__ __launch_bounds__(256, 2)
void rbf_mma_kernel(const float* __restrict__ X, const float* __restrict__ Y,
                    const float* __restrict__ gamma_p, const float* __restrict__ W,
                    float* __restrict__ out) {
    extern __shared__ char smem[];
    const uint32_t sb = smem_u32(smem);
    unsigned* nflag = (unsigned*)(smem + OFF_NF);
    unsigned* flags = (unsigned*)(smem + OFF_FLAGS);
    const int tid = threadIdx.x;
    const int w = tid >> 5, l = tid & 31;
    const int wm = w & 3, wn = w >> 2;         // 4 x 2 warp grid
    const int m0w = wm * 32, n0w = wn * 64;
    const int bn = blockIdx.x, bm = blockIdx.y;
    const int rowBase = bm * BM, colBase = bn * BN;

    if (tid < 128) ((float*)(smem + OFF_Q))[tid] = g_yyp[colBase + tid];
    if (tid == 0) *nflag = 0;

    // Certificate: sq_true >= (sqrt(sq~) - ef)^2 >= 0.75*sq~ - 3*ef^2 (AM-GM).
    // Sufficient: sq~ >= T = (110/gamma + 4*ef^2)*4/3 + 16 (slack: accum error).
    const float g = gamma_p[0];
    const float ef = __uint_as_float(g_Emax_bits) + __uint_as_float(g_Fmax_bits);
    const float T = (110.0f / g + 4.0f * ef * ef) * (4.0f / 3.0f) + 16.0f;

    float acc[2][8][4];
    #pragma unroll
    for (int mt = 0; mt < 2; mt++)
        #pragma unroll
        for (int nt = 0; nt < 8; nt++)
            #pragma unroll
            for (int i = 0; i < 4; i++) acc[mt][nt][i] = 0.0f;

    load_stage(sb, 0, 0, rowBase, colBase, tid); CP_COMMIT();
    load_stage(sb, 1, 1, rowBase, colBase, tid); CP_COMMIT();

    const uint32_t a_lane = (uint32_t)((m0w + (l & 15)) * ROW_PITCH + ((l >> 4) * 16));
    const uint32_t b_lane = (uint32_t)(STG_TILE + (n0w + (l & 15)) * ROW_PITCH + ((l >> 4) * 16));

    #pragma unroll 1
    for (int c = 0; c < NCHUNK; c++) {
        if (c == NCHUNK - 1) asm volatile("cp.async.wait_group 0;" ::: "memory");
        else                 asm volatile("cp.async.wait_group 1;" ::: "memory");
        __syncthreads();
        if (c + 2 < NCHUNK) {
            load_stage(sb, (c + 2) % STAGES, c + 2, rowBase, colBase, tid);
            CP_COMMIT();
        }
        const uint32_t stg = sb + (uint32_t)((c % STAGES) * STG_BYTES);
        #pragma unroll
        for (int kk = 0; kk < 2; kk++) {
            const uint32_t ko = (uint32_t)(kk * 32);
            uint32_t a[2][4], b[4][4];
            #pragma unroll
            for (int mt = 0; mt < 2; mt++)
                ldmatrix_x4(a[mt][0], a[mt][1], a[mt][2], a[mt][3],
                            stg + a_lane + mt * (16 * ROW_PITCH) + ko);
            #pragma unroll
            for (int nt2 = 0; nt2 < 4; nt2++)
                ldmatrix_x4(b[nt2][0], b[nt2][1], b[nt2][2], b[nt2][3],
                            stg + b_lane + nt2 * (16 * ROW_PITCH) + ko);
            #pragma unroll
            for (int mt = 0; mt < 2; mt++)
                #pragma unroll
                for (int nt = 0; nt < 8; nt++) {
                    const int h = nt >> 1, o = nt & 1;
                    mma_fp8(acc[mt][nt], a[mt][0], a[mt][1], a[mt][2], a[mt][3],
                            b[h][o], b[h][o + 2]);
                }
        }
    }

    // ---- epilogue: one compare per element; collect rare failures in smem ----
    const float* qsh = (const float*)(smem + OFF_Q);
    float xxp[2][2];
    #pragma unroll
    for (int mt = 0; mt < 2; mt++)
        #pragma unroll
        for (int h = 0; h < 2; h++)
            xxp[mt][h] = g_xxp[rowBase + m0w + mt * 16 + (l >> 2) + 8 * h];

    #pragma unroll
    for (int mt = 0; mt < 2; mt++)
        #pragma unroll
        for (int nt = 0; nt < 8; nt++) {
            const int nl = n0w + nt * 8 + (l & 3) * 2;
            const float yy0 = qsh[nl], yy1 = qsh[nl + 1];
            const int n = colBase + nl;
            const int m_lo = rowBase + m0w + mt * 16 + (l >> 2);
            const float* cc = acc[mt][nt];
            #pragma unroll
            for (int e = 0; e < 4; e++) {
                const float s = fmaf(-2.0f, cc[e],
                                     xxp[mt][e >> 1] + ((e & 1) ? yy1 : yy0));
                if (s < T) {
                    const int m = m_lo + (e >> 1) * 8;
                    const int nn = n + (e & 1);
                    const unsigned idx = atomicAdd(nflag, 1u);
                    if (idx < FCAP) flags[idx] = ((unsigned)m << 13) | (unsigned)nn;
                    else exact_term(X, Y, W, out, g, m, nn);  // overflow: inline exact
                }
            }
        }
    __syncthreads();

    // ---- inline exact fallback: one warp per flagged pair ----
    const int nf = (int)min(*nflag, (unsigned)FCAP);
    for (int i = w; i < nf; i += 8) {
        const unsigned pk = flags[i];
        const int m = (int)(pk >> 13), n = (int)(pk & 8191u);
        const float* xr = X + (size_t)m * D_DIM;
        const float* yr = Y + (size_t)n * D_DIM;
        float dot = 0.0f;
        #pragma unroll
        for (int d4 = 0; d4 < 4; d4++) {
            const int d = (l + d4 * 32) * 4;
            const float4 a = *(const float4*)(xr + d);
            const float4 b = *(const float4*)(yr + d);
            dot += a.x * b.x + a.y * b.y + a.z * b.z + a.w * b.w;
        }
        #pragma unroll
        for (int off = 16; off > 0; off >>= 1)
            dot += __shfl_down_sync(0xffffffffu, dot, off);
        if (l == 0) {
            const float sq = fmaxf(g_xx[m] + g_yy[n] - 2.0f * dot, 0.0f);
            atomicAdd(&out[m], __expf(-g * sq) * W[n]);
        }
    }
}

// ---------------------------------------------------------------------------
extern "C" void kernel_launch(void* const* d_in, const int* in_sizes, int n_in,
                              void* d_out, int out_size) {
    const float* x       = (const float*)d_in[0];
    const float* x_train = (const float*)d_in[1];
    const float* gamma   = (const float*)d_in[2];
    const float* weight  = (const float*)d_in[3];
    const float* bias    = (const float*)d_in[4];
    float* out = (float*)d_out;

    cudaFuncSetAttribute(rbf_mma_kernel, cudaFuncAttributeMaxDynamicSharedMemorySize, SMEM_BYTES);

    prep_kernel<<<dim3(M_DIM, 2), 128>>>(x, x_train);
    bias_kernel<<<M_DIM / 256, 256>>>(out, bias);
    rbf_mma_kernel<<<dim3(NBN, M_DIM / BM), 256, SMEM_BYTES>>>(x, x_train, gamma, weight, out);
}